// round 15
// baseline (speedup 1.0000x reference)
#include <cuda_runtime.h>
#include <math.h>
#include <stdint.h>

// Problem dims
#define Bc 64
#define Tc 512
#define Ic 512
#define Hc 1024
#define Oc 512
#define NCTA 128   // persistent grid (<=148 SMs -> all co-resident)

// Recurrence decomposition
#define NT 8       // column tiles of 128
#define KC 16      // K chunks of 64
#define KCH 64     // k per chunk
#define CT 128     // cols per tile

// ---- tf32 helpers (big GEMMs) ----
__device__ __forceinline__ uint32_t f2tf32(float x) {
    uint32_t r; asm("cvt.rna.tf32.f32 %0, %1;" : "=r"(r) : "f"(x)); return r;
}
__device__ __forceinline__ void mma_tf32(float* c,
                                         const uint32_t* a, const uint32_t* b) {
    asm("mma.sync.aligned.m16n8k8.row.col.f32.tf32.tf32.f32 "
        "{%0,%1,%2,%3}, {%4,%5,%6,%7}, {%8,%9}, {%0,%1,%2,%3};"
        : "+f"(c[0]), "+f"(c[1]), "+f"(c[2]), "+f"(c[3])
        : "r"(a[0]), "r"(a[1]), "r"(a[2]), "r"(a[3]), "r"(b[0]), "r"(b[1]));
}

// ---- bf16 helpers (recurrence) ----
__device__ __forceinline__ void split_bf16x2(float x, float y,
                                             uint32_t& hi, uint32_t& lo) {
    uint32_t h;
    asm("cvt.rn.bf16x2.f32 %0, %1, %2;" : "=r"(h) : "f"(y), "f"(x));
    float xh = __uint_as_float(h << 16);
    float yh = __uint_as_float(h & 0xFFFF0000u);
    asm("cvt.rn.bf16x2.f32 %0, %1, %2;" : "=r"(lo) : "f"(y - yh), "f"(x - xh));
    hi = h;
}
__device__ __forceinline__ void mma_bf16(float* c,
                                         const uint32_t* a, const uint32_t* b) {
    asm("mma.sync.aligned.m16n8k16.row.col.f32.bf16.bf16.f32 "
        "{%0,%1,%2,%3}, {%4,%5,%6,%7}, {%8,%9}, {%0,%1,%2,%3};"
        : "+f"(c[0]), "+f"(c[1]), "+f"(c[2]), "+f"(c[3])
        : "r"(a[0]), "r"(a[1]), "r"(a[2]), "r"(a[3]), "r"(b[0]), "r"(b[1]));
}
__device__ __forceinline__ void ldsm_x4(uint32_t* r, uint32_t addr) {
    asm volatile("ldmatrix.sync.aligned.m8n8.x4.shared.b16 {%0,%1,%2,%3}, [%4];"
        : "=r"(r[0]), "=r"(r[1]), "=r"(r[2]), "=r"(r[3]) : "r"(addr));
}
__device__ __forceinline__ void ldsm_x2(uint32_t* r, uint32_t addr) {
    asm volatile("ldmatrix.sync.aligned.m8n8.x2.shared.b16 {%0,%1}, [%2];"
        : "=r"(r[0]), "=r"(r[1]) : "r"(addr));
}
__device__ __forceinline__ uint32_t smem_u32(const void* p) {
    uint32_t a;
    asm("{ .reg .u64 t; cvta.to.shared.u64 t, %1; cvt.u32.u64 %0, t; }"
        : "=r"(a) : "l"(p));
    return a;
}

// Scratch (static __device__ allowed; cudaMalloc is not)
__device__ float g_xw[Tc * Bc * Hc];        // [t][b][h]  x@W_xh + b_h
__device__ float g_hall[Tc * Bc * Hc];      // [t][b][h]  hidden states (fp32)
__device__ float g_part[KC * Bc * Hc];      // [kc][b][h] per-K-chunk partials
__device__ __align__(16) uint16_t g_hr_hi[2 * Bc * Hc];  // ring: bf16 hi of h
__device__ __align__(16) uint16_t g_hr_lo[2 * Bc * Hc];  // ring: bf16 lo of h
__device__ unsigned g_bar;

// ---------------------------------------------------------------------------
__global__ void k_init() {
    if (threadIdx.x == 0) g_bar = 0u;
}

// ---------------------------------------------------------------------------
// Shared tf32 GEMM body, double-buffered (2-stage smem ping-pong, 1 sync/tile,
// next tile's global loads issued before the MMA block).
// ---------------------------------------------------------------------------
#define GEMM_TF32_BODY(Aptr, Bptr, Kdim, Ndim)                                  \
    __shared__ uint32_t As[2][128][20];                                         \
    __shared__ uint32_t Bs[2][16][136];                                         \
    const int tid  = threadIdx.x;                                               \
    const int lane = tid & 31;                                                  \
    const int warp = tid >> 5;                                                  \
    const int wm = warp & 1, wn = warp >> 1;                                    \
    const int m0 = blockIdx.y * 128;                                            \
    const int n0 = blockIdx.x * 128;                                            \
    int arow[2], akq[2], brow[2], bnq[2];                                       \
    _Pragma("unroll") for (int i = 0; i < 2; ++i) {                             \
        int g = tid + i * 256;                                                  \
        arow[i] = g >> 2; akq[i] = (g & 3) * 4;                                 \
        brow[i] = g >> 5; bnq[i] = (g & 31) * 4;                                \
    }                                                                           \
    float acc[4][4][4];                                                         \
    _Pragma("unroll") for (int mi = 0; mi < 4; ++mi)                            \
    _Pragma("unroll") for (int ni = 0; ni < 4; ++ni)                            \
    _Pragma("unroll") for (int q = 0; q < 4; ++q) acc[mi][ni][q] = 0.f;         \
    float4 av[2], bv[2];                                                        \
    _Pragma("unroll") for (int i = 0; i < 2; ++i) {                             \
        av[i] = *(const float4*)&(Aptr)[(size_t)(m0 + arow[i]) * (Kdim)         \
                                        + akq[i]];                              \
        bv[i] = *(const float4*)&(Bptr)[(size_t)brow[i] * (Ndim)                \
                                        + n0 + bnq[i]];                         \
    }                                                                           \
    _Pragma("unroll") for (int i = 0; i < 2; ++i) {                             \
        *(uint4*)&As[0][arow[i]][akq[i]] =                                      \
            make_uint4(f2tf32(av[i].x), f2tf32(av[i].y),                        \
                       f2tf32(av[i].z), f2tf32(av[i].w));                       \
        *(uint4*)&Bs[0][brow[i]][bnq[i]] =                                      \
            make_uint4(f2tf32(bv[i].x), f2tf32(bv[i].y),                        \
                       f2tf32(bv[i].z), f2tf32(bv[i].w));                       \
    }                                                                           \
    __syncthreads();                                                            \
    int p = 0;                                                                  \
    for (int k0 = 0; k0 < (Kdim); k0 += 16) {                                   \
        const bool hn = (k0 + 16) < (Kdim);                                     \
        if (hn) {                                                               \
            _Pragma("unroll") for (int i = 0; i < 2; ++i) {                     \
                av[i] = *(const float4*)&(Aptr)[(size_t)(m0 + arow[i]) * (Kdim) \
                                                + k0 + 16 + akq[i]];            \
                bv[i] = *(const float4*)&(Bptr)[(size_t)(k0 + 16 + brow[i])     \
                                                * (Ndim) + n0 + bnq[i]];        \
            }                                                                   \
        }                                                                       \
        _Pragma("unroll") for (int kb = 0; kb < 16; kb += 8) {                  \
            uint32_t afr[4][4];                                                 \
            _Pragma("unroll") for (int mi = 0; mi < 4; ++mi) {                  \
                int r = (lane >> 2) + mi * 16 + wm * 64;                        \
                int kk = kb + (lane & 3);                                       \
                afr[mi][0] = As[p][r][kk];                                      \
                afr[mi][1] = As[p][r + 8][kk];                                  \
                afr[mi][2] = As[p][r][kk + 4];                                  \
                afr[mi][3] = As[p][r + 8][kk + 4];                              \
            }                                                                   \
            uint32_t bfr[4][2];                                                 \
            _Pragma("unroll") for (int ni = 0; ni < 4; ++ni) {                  \
                int c = (lane >> 2) + ni * 8 + wn * 32;                         \
                bfr[ni][0] = Bs[p][kb + (lane & 3)][c];                         \
                bfr[ni][1] = Bs[p][kb + (lane & 3) + 4][c];                     \
            }                                                                   \
            _Pragma("unroll") for (int mi = 0; mi < 4; ++mi)                    \
            _Pragma("unroll") for (int ni = 0; ni < 4; ++ni)                    \
                mma_tf32(acc[mi][ni], afr[mi], bfr[ni]);                        \
        }                                                                       \
        if (hn) {                                                               \
            _Pragma("unroll") for (int i = 0; i < 2; ++i) {                     \
                *(uint4*)&As[p ^ 1][arow[i]][akq[i]] =                          \
                    make_uint4(f2tf32(av[i].x), f2tf32(av[i].y),                \
                               f2tf32(av[i].z), f2tf32(av[i].w));               \
                *(uint4*)&Bs[p ^ 1][brow[i]][bnq[i]] =                          \
                    make_uint4(f2tf32(bv[i].x), f2tf32(bv[i].y),                \
                               f2tf32(bv[i].z), f2tf32(bv[i].w));               \
            }                                                                   \
        }                                                                       \
        __syncthreads();                                                        \
        p ^= 1;                                                                 \
    }

// GEMM 1: g_xw[t*B+b][h] = x[b*T+t][:] @ W_xh + b_h.  M=32768,N=1024,K=512
__global__ void __launch_bounds__(256) k_gemm_xw(const float* __restrict__ A,
                                                 const float* __restrict__ Bm,
                                                 const float* __restrict__ bias) {
    GEMM_TF32_BODY(A, Bm, Ic, Hc)
#pragma unroll
    for (int mi = 0; mi < 4; ++mi)
#pragma unroll
        for (int ni = 0; ni < 4; ++ni) {
            int r = m0 + wm * 64 + mi * 16 + (lane >> 2);
            int c = n0 + wn * 32 + ni * 8 + 2 * (lane & 3);
            float bx = bias[c], by = bias[c + 1];
            int b1i = r >> 9, t1i = r & 511;
            float* d0 = g_xw + (size_t)(t1i * Bc + b1i) * Hc + c;
            d0[0] = acc[mi][ni][0] + bx; d0[1] = acc[mi][ni][1] + by;
            int r2 = r + 8;
            int b2i = r2 >> 9, t2i = r2 & 511;
            float* d1 = g_xw + (size_t)(t2i * Bc + b2i) * Hc + c;
            d1[0] = acc[mi][ni][2] + bx; d1[1] = acc[mi][ni][3] + by;
        }
}

// GEMM 2: out[b][t][o] = g_hall[t*B+b][:] @ W_hy + b_y.  M=32768,N=512,K=1024
__global__ void __launch_bounds__(256) k_gemm_y(const float* __restrict__ Bm,
                                                const float* __restrict__ bias,
                                                float* __restrict__ out) {
    const float* A = g_hall;
    GEMM_TF32_BODY(A, Bm, Hc, Oc)
#pragma unroll
    for (int mi = 0; mi < 4; ++mi)
#pragma unroll
        for (int ni = 0; ni < 4; ++ni) {
            int r = m0 + wm * 64 + mi * 16 + (lane >> 2);
            int c = n0 + wn * 32 + ni * 8 + 2 * (lane & 3);
            float bx = bias[c], by = bias[c + 1];
            int t1i = r >> 6, b1i = r & 63;
            float* d0 = out + ((size_t)b1i * Tc + t1i) * Oc + c;
            d0[0] = acc[mi][ni][0] + bx; d0[1] = acc[mi][ni][1] + by;
            int r2 = r + 8;
            int t2i = r2 >> 6, b2i = r2 & 63;
            float* d1 = out + ((size_t)b2i * Tc + t2i) * Oc + c;
            d1[0] = acc[mi][ni][2] + bx; d1[1] = acc[mi][ni][3] + by;
        }
}

// ---------------------------------------------------------------------------
// Persistent recurrence, K-split two-phase, bf16x3 m16n8k16, ldmatrix frags.
// NOW 512 threads (16 warps, 4/SMSP) for HMMA latency hiding.
// CTA (jt, kc): partial[64][128] = h_prev[:, kc*64:+64] @ Whh[kc*64:+64, jt*128:+128]
// Warp w owns 8 cols (w*8..w*8+7). Same arithmetic as round 14 (bit-exact).
// ---------------------------------------------------------------------------
__global__ void __launch_bounds__(512, 1) k_rnn(const float* __restrict__ Whh) {
    extern __shared__ uint32_t smu[];
    uint32_t* w_hi = smu;                       // [128 n][36]
    uint32_t* w_lo = smu + 128 * 36;            // [128 n][36]
    uint32_t* h_hi = smu + 2 * 128 * 36;        // [64 r][36]
    uint32_t* h_lo = smu + 2 * 128 * 36 + 64 * 36;

    const int tid  = threadIdx.x;
    const int lane = tid & 31;
    const int warp = tid >> 5;                  // 0..15 -> 8 cols each
    const int cta = blockIdx.x;
    const int jt = cta & (NT - 1);              // 0..7
    const int kc = cta >> 3;                    // 0..15

    // Preload W_hh slice, split + pack (k even -> lower, k+1 -> upper)
    for (int e = tid; e < CT * (KCH / 2); e += 512) {
        int n = e & 127, k2 = e >> 7;           // k2 0..31
        const float* wp = Whh + (size_t)(kc * KCH + 2 * k2) * Hc + jt * CT + n;
        uint32_t hi, lo;
        split_bf16x2(wp[0], wp[Hc], hi, lo);
        w_hi[n * 36 + k2] = hi;
        w_lo[n * 36 + k2] = lo;
    }

    // smem u32 bases for ldmatrix
    const uint32_t sb     = smem_u32(smu);
    const uint32_t sb_whi = sb;
    const uint32_t sb_wlo = sb + 128 * 36 * 4;
    const uint32_t sb_hhi = sb + 2 * 128 * 36 * 4;
    const uint32_t sb_hlo = sb_hhi + 64 * 36 * 4;

    // A (m16k16 x4): lanes 0-7 rows 0-7 kh0 | 8-15 rows 8-15 kh0
    //                | 16-23 rows 0-7 kh1 | 24-31 rows 8-15 kh1
    const uint32_t a_loff = (uint32_t)(((lane & 15) * 36 + (lane >> 4) * 4) * 4);
    // B (n8k16 x2): lanes 0-7 n0-7 kh0 | 8-15 n0-7 kh1
    const uint32_t b_loff = (uint32_t)((((lane & 7) * 36) + ((lane >> 3) & 1) * 4) * 4);
    const uint32_t b_warp = (uint32_t)(warp * 8 * 36 * 4);

    // Phase B mapping: 65536 threads, each 1 row x 1 col of h
    const int gid = cta * 512 + tid;
    const int brow = gid >> 10;                 // 0..63
    const int bcol = gid & 1023;                // 0..1023

    unsigned target = 0;

    for (int t = 0; t < Tc; ++t) {
        // ================= Phase A =================
        if (t > 0) {
            const int ring = (t - 1) & 1;
            const uint16_t* phi = g_hr_hi + (size_t)ring * (Bc * Hc);
            const uint16_t* plo = g_hr_lo + (size_t)ring * (Bc * Hc);
            // 512 uint4 groups (8 bf16 each): r = tid>>3, k-offset (tid&7)*8
            {
                int r = tid >> 3, kq = (tid & 7) * 4;  // kq in words
                size_t src = (size_t)r * Hc + kc * KCH + (tid & 7) * 8;
                uint4 vh = __ldcg((const uint4*)(phi + src));
                uint4 vl = __ldcg((const uint4*)(plo + src));
                *(uint4*)&h_hi[r * 36 + kq] = vh;
                *(uint4*)&h_lo[r * 36 + kq] = vl;
            }
            __syncthreads();

            float acc[4][4];
#pragma unroll
            for (int mi = 0; mi < 4; ++mi)
#pragma unroll
                for (int q = 0; q < 4; ++q) acc[mi][q] = 0.f;

#pragma unroll
            for (int s = 0; s < 4; ++s) {       // four k16 slabs
                const uint32_t soff = (uint32_t)(8 * s * 4);
                uint32_t ahi[4][4], alo[4][4];
#pragma unroll
                for (int mi = 0; mi < 4; ++mi) {
                    const uint32_t moff = (uint32_t)(mi * 16 * 36 * 4);
                    ldsm_x4(ahi[mi], sb_hhi + moff + soff + a_loff);
                    ldsm_x4(alo[mi], sb_hlo + moff + soff + a_loff);
                }
                uint32_t bhi[2], blo[2];
                ldsm_x2(bhi, sb_whi + b_warp + soff + b_loff);
                ldsm_x2(blo, sb_wlo + b_warp + soff + b_loff);
#pragma unroll
                for (int mi = 0; mi < 4; ++mi) {
                    mma_bf16(acc[mi], ahi[mi], bhi);   // hi*Whi
                    mma_bf16(acc[mi], ahi[mi], blo);   // hi*Wlo
                    mma_bf16(acc[mi], alo[mi], bhi);   // lo*Whi
                }
            }
            // write partials: g_part[kc][row][jt*128 + warp*8 + col]
#pragma unroll
            for (int mi = 0; mi < 4; ++mi) {
                int row = (lane >> 2) + mi * 16;
                int col = warp * 8 + 2 * (lane & 3);
                float* p = g_part + (size_t)kc * (Bc * Hc)
                         + (size_t)row * Hc + jt * CT + col;
                *(float2*)p = make_float2(acc[mi][0], acc[mi][1]);
                *(float2*)(p + 8 * Hc) = make_float2(acc[mi][2], acc[mi][3]);
            }
        }

        // prefetch xw for phase B (independent; hides under barrier)
        float sx = g_xw[(size_t)t * (Bc * Hc) + (size_t)brow * Hc + bcol];

        // ---- grid barrier 1 ----
        target += NCTA;
        __syncthreads();
        if (tid == 0) {
            __threadfence();
            atomicAdd(&g_bar, 1u);
            while (*((volatile unsigned*)&g_bar) < target) { }
            __threadfence();
        }
        __syncthreads();

        // ================= Phase B =================
        {
            if (t > 0) {
                const float* pb = g_part + (size_t)brow * Hc + bcol;
#pragma unroll
                for (int k2 = 0; k2 < KC; ++k2)
                    sx += __ldcg(pb + (size_t)k2 * (Bc * Hc));
            }
            float hx = tanhf(sx);
            size_t dst = (size_t)brow * Hc + bcol;
            g_hall[(size_t)t * (Bc * Hc) + dst] = hx;
            // exact bf16 split for next step's phase A (ring slot t&1)
            uint32_t hi, lo;
            split_bf16x2(hx, 0.f, hi, lo);      // low 16 bits hold bf16(hx)
            size_t rb = (size_t)(t & 1) * (Bc * Hc) + dst;
            g_hr_hi[rb] = (uint16_t)(hi & 0xFFFFu);
            g_hr_lo[rb] = (uint16_t)(lo & 0xFFFFu);
        }

        // ---- grid barrier 2 ----
        target += NCTA;
        __syncthreads();
        if (tid == 0) {
            __threadfence();
            atomicAdd(&g_bar, 1u);
            while (*((volatile unsigned*)&g_bar) < target) { }
            __threadfence();
        }
        __syncthreads();
    }
}

// ---------------------------------------------------------------------------
extern "C" void kernel_launch(void* const* d_in, const int* in_sizes, int n_in,
                              void* d_out, int out_size) {
    const float* x    = (const float*)d_in[0];  // [64,512,512]
    const float* W_xh = (const float*)d_in[1];  // [512,1024]
    const float* W_hh = (const float*)d_in[2];  // [1024,1024]
    const float* b_h  = (const float*)d_in[3];  // [1024]
    const float* W_hy = (const float*)d_in[4];  // [1024,512]
    const float* b_y  = (const float*)d_in[5];  // [512]
    float* out = (float*)d_out;                 // [64,512,512]

    // smem: W hi/lo [128][36] + h hi/lo [64][36]  (uint32) = 54KB
    const int rnn_smem = (2 * 128 * 36 + 2 * 64 * 36) * (int)sizeof(uint32_t);

    static bool attr_set = false;
    if (!attr_set) {
        cudaFuncSetAttribute(k_rnn, cudaFuncAttributeMaxDynamicSharedMemorySize,
                             rnn_smem);
        attr_set = true;
    }

    k_init<<<1, 32>>>();

    // xW projection: M=32768, N=1024 (tf32 MMA, double-buffered)
    dim3 gx(Hc / 128, (Bc * Tc) / 128);
    k_gemm_xw<<<gx, 256>>>(x, W_xh, b_h);

    // recurrence: persistent, 128 CTAs x 512 thr, two-phase K-split
    k_rnn<<<NCTA, 512, rnn_smem>>>(W_hh);

    // output projection: M=32768, N=512 (tf32 MMA, double-buffered)
    dim3 gy(Oc / 128, (Bc * Tc) / 128);
    k_gemm_y<<<gy, 256>>>(W_hy, b_y, out);
}